// round 7
// baseline (speedup 1.0000x reference)
#include <cuda_runtime.h>
#include <math.h>

constexpr int   NELEM  = 8192;
constexpr int   NB     = 256;            // psi buckets
constexpr int   BCAP   = 96;             // slots per bucket (mean 32, +11 sigma)
constexpr int   PBLK   = 64;             // prep blocks
constexpr int   PTPB   = 128;            // prep threads
constexpr int   NSY    = 4;              // window slices per bucket
constexpr int   TPB    = 128;            // pairs threads
constexpr int   NBLK   = NB * NSY;       // 1024 pairs blocks
constexpr int   SHCAP  = 1536;           // shared window cap (float2) = 12 KB
constexpr int   WMARG  = 13;             // 13/256 = 0.0508 > 0.05
constexpr float THRESH = 0.05f;
constexpr float MSEW   = 10.0f;
constexpr float LEPS   = 1e-7f;

// ---- device scratch; g_bcnt/g_arr self-reset at end of each replay ----
__device__ float2   g_bucket[NB][BCAP];
__device__ int      g_bcnt[NB];
__device__ float    g_md[PBLK], g_md2[PBLK], g_mb[PBLK];
__device__ float    g_ps[NBLK];
__device__ int      g_pc[NBLK];
__device__ unsigned g_arr;

// ================= kernel A: pd -> buckets, moments, BCE =================
__global__ void __launch_bounds__(PTPB)
prep(const float* __restrict__ pred, const float* __restrict__ psi) {
    const int tid = threadIdx.x;
    const int bid = blockIdx.x;
    const int i   = bid * PTPB + tid;

    float x = __ldg(&pred[i]);
    float y = __ldg(&psi[i]);
    float p = fminf(fmaxf(y, LEPS), 1.0f - LEPS);
    float d = x - __logf(__fdividef(p, 1.0f - p));
    int   b = min(NB - 1, max(0, (int)(y * (float)NB)));

    int pos = atomicAdd(&g_bcnt[b], 1);          // global atomics, chip-wide spread
    if (pos < BCAP) g_bucket[b][pos] = make_float2(y, d);

    float sd  = d;
    float sd2 = d * d;
    float sb  = fmaxf(x, 0.f) - x * y + __logf(1.0f + __expf(-fabsf(x)));

    #pragma unroll
    for (int o = 16; o > 0; o >>= 1) {
        sd  += __shfl_down_sync(0xffffffffu, sd,  o);
        sd2 += __shfl_down_sync(0xffffffffu, sd2, o);
        sb  += __shfl_down_sync(0xffffffffu, sb,  o);
    }
    __shared__ float rf[3][PTPB / 32];
    if ((tid & 31) == 0) { rf[0][tid >> 5] = sd; rf[1][tid >> 5] = sd2; rf[2][tid >> 5] = sb; }
    __syncthreads();
    if (tid == 0) {
        float a = 0.f, c = 0.f, e = 0.f;
        #pragma unroll
        for (int w = 0; w < PTPB / 32; ++w) { a += rf[0][w]; c += rf[1][w]; e += rf[2][w]; }
        g_md[bid] = a; g_md2[bid] = c; g_mb[bid] = e;
    }
}

// ============ kernel B: invalid-pair window scan + finalize ============
__global__ void __launch_bounds__(TPB)
pairs(const int* __restrict__ flag, float* __restrict__ out) {
    __shared__ float2 win[SHCAP];
    __shared__ int    soff[34];
    __shared__ float  shs[TPB / 32];
    __shared__ int    shc[TPB / 32];
    __shared__ int    sh_last;

    const int tid  = threadIdx.x;
    const int lane = tid & 31;
    const int wrp  = tid >> 5;
    const int b    = blockIdx.x;
    const int sy   = blockIdx.y;

    const int b0  = max(0, b - WMARG);
    const int b1  = min(NB, b + WMARG + 1);
    const int nbk = b1 - b0;                     // <= 27

    // warp 0: bucket counts + inclusive scan -> soff[]
    if (tid < 32) {
        int c = (tid < nbk) ? min(__ldcg(&g_bcnt[b0 + tid]), BCAP) : 0;
        int incl = c;
        #pragma unroll
        for (int o = 1; o < 32; o <<= 1) {
            int t = __shfl_up_sync(0xffffffffu, incl, o);
            if (lane >= o) incl += t;
        }
        soff[tid + 1] = incl;
        if (tid == 0) soff[0] = 0;
    }
    __syncthreads();

    const int total = soff[nbk];
    const int tl    = min(total, SHCAP);

    // ragged copy: window buckets -> contiguous shared
    for (int bb = 0; bb < nbk; ++bb) {
        int base = soff[bb];
        int c    = soff[bb + 1] - base;
        for (int k = tid; k < c; k += TPB)
            if (base + k < SHCAP) win[base + k] = g_bucket[b0 + bb][k];
    }
    __syncthreads();

    // my bucket's i elements live inside the window
    const int iob = soff[b - b0];
    const int myc = min(soff[b - b0 + 1], tl) - min(iob, tl);
    const int s16 = sy * 4 + wrp;                // 16-way window split
    const int jw0 = (tl * s16)       >> 4;
    const int jw1 = (tl * (s16 + 1)) >> 4;

    float sacc = 0.f; int cacc = 0;
    for (int ii = lane; ii < myc; ii += 32) {
        float2 pi = win[iob + ii];
        float yi = pi.x, di = pi.y;
        float s = 0.f; int c = 0;
        #pragma unroll 4
        for (int j = jw0; j < jw1; ++j) {
            float2 pj = win[j];                  // broadcast LDS.64
            float dp = yi - pj.x;
            float dd = di - pj.y;
            if (fabsf(dp) < THRESH) { s = fmaf(dd, dd, s); c++; }
        }
        sacc += s; cacc += c;
    }

    // block reduction -> slot
    #pragma unroll
    for (int o = 16; o > 0; o >>= 1) {
        sacc += __shfl_down_sync(0xffffffffu, sacc, o);
        cacc += __shfl_down_sync(0xffffffffu, cacc, o);
    }
    if (lane == 0) { shs[wrp] = sacc; shc[wrp] = cacc; }
    __syncthreads();
    if (tid == 0) {
        float fs = 0.f; int fc = 0;
        #pragma unroll
        for (int w = 0; w < TPB / 32; ++w) { fs += shs[w]; fc += shc[w]; }
        int slot = sy * NB + b;
        g_ps[slot] = fs; g_pc[slot] = fc;
        __threadfence();
        sh_last = (atomicAdd(&g_arr, 1u) == (unsigned)(NBLK - 1));
        if (sh_last) __threadfence();
    }
    __syncthreads();
    if (!sh_last) return;

    // -------- finalize in last-arriving block --------
    double dsi = 0.0, ds = 0.0, ds2 = 0.0, db = 0.0;
    long long ci = 0;
    for (int k = tid; k < NBLK; k += TPB) {
        dsi += (double)__ldcg(&g_ps[k]);
        ci  += (long long)__ldcg(&g_pc[k]);
    }
    for (int k = tid; k < PBLK; k += TPB) {
        ds  += (double)__ldcg(&g_md[k]);
        ds2 += (double)__ldcg(&g_md2[k]);
        db  += (double)__ldcg(&g_mb[k]);
    }
    #pragma unroll
    for (int o = 16; o > 0; o >>= 1) {
        dsi += __shfl_down_sync(0xffffffffu, dsi, o);
        ci  += __shfl_down_sync(0xffffffffu, ci,  o);
        ds  += __shfl_down_sync(0xffffffffu, ds,  o);
        ds2 += __shfl_down_sync(0xffffffffu, ds2, o);
        db  += __shfl_down_sync(0xffffffffu, db,  o);
    }
    __shared__ double    shd[4][TPB / 32];
    __shared__ long long shl[TPB / 32];
    if (lane == 0) {
        shd[0][wrp] = dsi; shd[1][wrp] = ds; shd[2][wrp] = ds2; shd[3][wrp] = db;
        shl[wrp] = ci;
    }
    __syncthreads();
    if (tid == 0) {
        double Sinv = 0.0, Sd = 0.0, Sd2 = 0.0, Sb = 0.0; long long Cinv = 0;
        #pragma unroll
        for (int w = 0; w < TPB / 32; ++w) {
            Sinv += shd[0][w]; Sd += shd[1][w]; Sd2 += shd[2][w]; Sb += shd[3][w];
            Cinv += shl[w];
        }
        double S_all = 2.0 * (double)NELEM * Sd2 - 2.0 * Sd * Sd;
        long long Cval = (long long)NELEM * (long long)NELEM - Cinv;
        float bce = (float)(Sb / (double)NELEM);
        int bce_only = (flag != nullptr) ? *flag : 0;
        float result;
        if (bce_only) {
            result = bce;
        } else {
            double Sval = S_all - Sinv;
            if (Sval < 0.0) Sval = 0.0;
            double mse = Sval / (double)(Cval > 0 ? Cval : 1);
            result = (Cval > 0) ? (bce + MSEW * (float)mse) : bce;
        }
        out[0] = result;
        g_arr = 0u;                               // reset for next replay
    }
    // reset bucket counters for next replay (all blocks are past reading them)
    for (int k = tid; k < NB; k += TPB) g_bcnt[k] = 0;
}

extern "C" void kernel_launch(void* const* d_in, const int* in_sizes, int n_in,
                              void* d_out, int out_size) {
    const float* pred = (const float*)d_in[0];
    const float* psi  = (const float*)d_in[1];
    const int*   flag = (n_in >= 3 && in_sizes[2] >= 1) ? (const int*)d_in[2] : nullptr;

    prep<<<PBLK, PTPB>>>(pred, psi);
    pairs<<<dim3(NB, NSY), TPB>>>(flag, (float*)d_out);
}

// round 8
// speedup vs baseline: 1.2756x; 1.2756x over previous
#include <cuda_runtime.h>
#include <math.h>

constexpr int   NELEM  = 8192;
constexpr int   NB     = 256;            // psi buckets
constexpr int   BCAP   = 96;             // slots/bucket (mean 32, +11 sigma)
constexpr int   PBLK   = 64;             // prep blocks
constexpr int   PTPB   = 128;
constexpr int   NSY    = 4;              // window slices per bucket
constexpr int   TPB    = 128;
constexpr int   NBLK   = NB * NSY;       // 1024 pairs blocks
constexpr int   WMARG  = 13;             // 13/256 = 0.0508 > 0.05
constexpr int   WBK    = 2 * WMARG + 1;  // 27 window buckets
constexpr int   MAXROW = 7;              // max bucket rows per block slice
constexpr float THRESH = 0.05f;
constexpr float MSEW   = 10.0f;
constexpr float LEPS   = 1e-7f;
constexpr float SENT   = 1.0e9f;

// device scratch; g_bcnt/g_arr self-reset in finalize each replay
__device__ float2   g_bucket[NB][BCAP];
__device__ int      g_bcnt[NB];
__device__ float    g_md[PBLK], g_md2[PBLK], g_mb[PBLK];
__device__ float    g_ps[NBLK];
__device__ int      g_pc[NBLK];
__device__ unsigned g_arr;

// ================= kernel A: pd -> buckets, moments, BCE =================
__global__ void __launch_bounds__(PTPB)
prep(const float* __restrict__ pred, const float* __restrict__ psi) {
    const int tid = threadIdx.x;
    const int bid = blockIdx.x;
    const int i   = bid * PTPB + tid;

    float x = __ldg(&pred[i]);
    float y = __ldg(&psi[i]);
    float p = fminf(fmaxf(y, LEPS), 1.0f - LEPS);
    float d = x - __logf(__fdividef(p, 1.0f - p));
    int   b = min(NB - 1, max(0, (int)(y * (float)NB)));

    int pos = atomicAdd(&g_bcnt[b], 1);
    if (pos < BCAP) g_bucket[b][pos] = make_float2(y, d);

    float sd  = d;
    float sd2 = d * d;
    float sb  = fmaxf(x, 0.f) - x * y + __logf(1.0f + __expf(-fabsf(x)));

    #pragma unroll
    for (int o = 16; o > 0; o >>= 1) {
        sd  += __shfl_down_sync(0xffffffffu, sd,  o);
        sd2 += __shfl_down_sync(0xffffffffu, sd2, o);
        sb  += __shfl_down_sync(0xffffffffu, sb,  o);
    }
    __shared__ float rf[3][PTPB / 32];
    if ((tid & 31) == 0) { rf[0][tid >> 5] = sd; rf[1][tid >> 5] = sd2; rf[2][tid >> 5] = sb; }
    __syncthreads();
    if (tid == 0) {
        float a = 0.f, c = 0.f, e = 0.f;
        #pragma unroll
        for (int w = 0; w < PTPB / 32; ++w) { a += rf[0][w]; c += rf[1][w]; e += rf[2][w]; }
        g_md[bid] = a; g_md2[bid] = c; g_mb[bid] = e;
    }
}

// ============ kernel B: invalid-pair window scan + finalize ============
__global__ void __launch_bounds__(TPB)
pairs(const int* __restrict__ flag, float* __restrict__ out) {
    __shared__ float2 win[MAXROW * BCAP];     // 672 float2 = 5.4 KB
    __shared__ int    scnt[MAXROW];
    __shared__ float  shs[TPB / 32];
    __shared__ int    shc[TPB / 32];
    __shared__ int    sh_last;

    const int tid  = threadIdx.x;
    const int lane = tid & 31;
    const int wrp  = tid >> 5;
    const int b    = blockIdx.x;
    const int sy   = blockIdx.y;

    // this block's (unclamped) bucket-row base and clamped copy range
    const int cb0u = b - WMARG + (WBK * (sy * 4))     / 16;
    const int cb1u = b - WMARG + (WBK * (sy * 4 + 4)) / 16;
    const int cb0c = max(cb0u, 0);
    const int cb1c = min(cb1u, NB);
    const int nrow = max(cb1c - cb0c, 0);

    // per-bucket counts -> shared
    if (tid < MAXROW) {
        int bb = cb0u + tid;
        scnt[tid] = (bb >= 0 && bb < NB) ? min(__ldcg(&g_bcnt[bb]), BCAP) : 0;
    }

    // flat coalesced copy of padded rows (padding copied, never read)
    {
        const int n   = nrow * BCAP;
        const int dst0 = (cb0c - cb0u) * BCAP;
        const float2* src = &g_bucket[cb0c][0];
        for (int t = tid; t < n; t += TPB) win[dst0 + t] = __ldcg(&src[t]);
    }

    // my bucket's i-slots: lane and lane+32 (register sentinel if past count)
    const int cnt_b = min(__ldcg(&g_bcnt[b]), BCAP);
    __syncthreads();

    // warp-slice of the window: 16-way split of the 27 buckets
    const int ws   = sy * 4 + wrp;
    const int wb0  = max(b - WMARG + (WBK * ws)       / 16, 0);
    const int wb1  = min(b - WMARG + (WBK * (ws + 1)) / 16, NB);

    float sacc = 0.f; int cacc = 0;
    for (int ii = 0; ii < cnt_b; ii += 64) {       // executes once in practice
        int i0 = ii + lane, i1 = ii + lane + 32;
        float2 p0 = (i0 < cnt_b) ? g_bucket[b][i0] : make_float2(SENT, 0.f);
        float2 p1 = (i1 < cnt_b) ? g_bucket[b][i1] : make_float2(SENT, 0.f);
        float y0 = p0.x, d0 = p0.y, y1 = p1.x, d1 = p1.y;

        float s0 = 0.f, s1 = 0.f, c1f = 0.f;
        int   c0 = 0;
        for (int bb = wb0; bb < wb1; ++bb) {
            const int c = scnt[bb - cb0u];
            const float2* base = &win[(bb - cb0u) * BCAP];
            #pragma unroll 4
            for (int k = 0; k < c; ++k) {
                float2 pj = base[k];               // broadcast LDS.64
                float dp0 = y0 - pj.x, dd0 = d0 - pj.y;
                float dp1 = y1 - pj.x, dd1 = d1 - pj.y;
                if (fabsf(dp0) < THRESH) { s0 = fmaf(dd0, dd0, s0); c0++; }
                if (fabsf(dp1) < THRESH) { s1 = fmaf(dd1, dd1, s1); c1f += 1.0f; }
            }
        }
        sacc += s0 + s1;
        cacc += c0 + (int)c1f;                     // c1f <= BCAP*WBK, exact in float
    }

    // block reduction -> slot
    #pragma unroll
    for (int o = 16; o > 0; o >>= 1) {
        sacc += __shfl_down_sync(0xffffffffu, sacc, o);
        cacc += __shfl_down_sync(0xffffffffu, cacc, o);
    }
    if (lane == 0) { shs[wrp] = sacc; shc[wrp] = cacc; }
    __syncthreads();
    if (tid == 0) {
        float fs = 0.f; int fc = 0;
        #pragma unroll
        for (int w = 0; w < TPB / 32; ++w) { fs += shs[w]; fc += shc[w]; }
        int slot = sy * NB + b;
        g_ps[slot] = fs; g_pc[slot] = fc;
        __threadfence();
        sh_last = (atomicAdd(&g_arr, 1u) == (unsigned)(NBLK - 1));
        if (sh_last) __threadfence();
    }
    __syncthreads();
    if (!sh_last) return;

    // -------- finalize in last-arriving block --------
    double dsi = 0.0, ds = 0.0, ds2 = 0.0, db = 0.0;
    long long ci = 0;
    for (int k = tid; k < NBLK; k += TPB) {
        dsi += (double)__ldcg(&g_ps[k]);
        ci  += (long long)__ldcg(&g_pc[k]);
    }
    for (int k = tid; k < PBLK; k += TPB) {
        ds  += (double)__ldcg(&g_md[k]);
        ds2 += (double)__ldcg(&g_md2[k]);
        db  += (double)__ldcg(&g_mb[k]);
    }
    #pragma unroll
    for (int o = 16; o > 0; o >>= 1) {
        dsi += __shfl_down_sync(0xffffffffu, dsi, o);
        ci  += __shfl_down_sync(0xffffffffu, ci,  o);
        ds  += __shfl_down_sync(0xffffffffu, ds,  o);
        ds2 += __shfl_down_sync(0xffffffffu, ds2, o);
        db  += __shfl_down_sync(0xffffffffu, db,  o);
    }
    __shared__ double    shd[4][TPB / 32];
    __shared__ long long shl[TPB / 32];
    if (lane == 0) {
        shd[0][wrp] = dsi; shd[1][wrp] = ds; shd[2][wrp] = ds2; shd[3][wrp] = db;
        shl[wrp] = ci;
    }
    __syncthreads();
    if (tid == 0) {
        double Sinv = 0.0, Sd = 0.0, Sd2 = 0.0, Sb = 0.0; long long Cinv = 0;
        #pragma unroll
        for (int w = 0; w < TPB / 32; ++w) {
            Sinv += shd[0][w]; Sd += shd[1][w]; Sd2 += shd[2][w]; Sb += shd[3][w];
            Cinv += shl[w];
        }
        double S_all = 2.0 * (double)NELEM * Sd2 - 2.0 * Sd * Sd;
        long long Cval = (long long)NELEM * (long long)NELEM - Cinv;
        float bce = (float)(Sb / (double)NELEM);
        int bce_only = (flag != nullptr) ? *flag : 0;
        float result;
        if (bce_only) {
            result = bce;
        } else {
            double Sval = S_all - Sinv;
            if (Sval < 0.0) Sval = 0.0;
            double mse = Sval / (double)(Cval > 0 ? Cval : 1);
            result = (Cval > 0) ? (bce + MSEW * (float)mse) : bce;
        }
        out[0] = result;
        g_arr = 0u;
    }
    for (int k = tid; k < NB; k += TPB) g_bcnt[k] = 0;   // reset for next replay
}

extern "C" void kernel_launch(void* const* d_in, const int* in_sizes, int n_in,
                              void* d_out, int out_size) {
    const float* pred = (const float*)d_in[0];
    const float* psi  = (const float*)d_in[1];
    const int*   flag = (n_in >= 3 && in_sizes[2] >= 1) ? (const int*)d_in[2] : nullptr;

    prep<<<PBLK, PTPB>>>(pred, psi);
    pairs<<<dim3(NB, NSY), TPB>>>(flag, (float*)d_out);
}